// round 7
// baseline (speedup 1.0000x reference)
#include <cuda_runtime.h>
#include <cuda_fp16.h>
#include <cstdint>

// out[32,14336] = (x * scales) @ W^T
//   x: [32,4096] f32, W: [14336,4096] int32 (|w|<=127), scales: [4096] f32
// HBM-bound: 235MB weight stream -> floor ~29.4us.
// R6 change: single-wave grid. 448 CTAs x 128 threads, occupancy 4/SM ->
// all CTAs resident at once (R5 ran 444 + a 4-CTA straggler wave that idled
// the chip for ~25% of the kernel). 4 warps/CTA split K; register-pipelined
// int4 weight loads keep enough bytes in flight at 12-16 warps/SM.

#define TOKENS 32
#define IN_F   4096
#define OUT_F  14336
#define NUM_KB (IN_F / 16)      // 256 k16-blocks

// A-fragments of xs=x*scales in fp16, fragment-major (permuted k-layout):
// index ((kb*2 + mi)*32 + lane) -> uint4 (8 fp16 = one m16k16 A frag slice)
__device__ uint4 g_xsfrag[NUM_KB * 2 * 32];

// ---------------------------------------------------------------------------
// Prep: build fragment-major fp16 xs with the permuted k-layout.
// lane quad q owns physical k = kb*16 + 4q .. 4q+3 (one contiguous float4).
// ---------------------------------------------------------------------------
__global__ __launch_bounds__(256) void prep_xs_kernel(
    const float* __restrict__ x, const float* __restrict__ scales)
{
    int wg   = blockIdx.x * (blockDim.x >> 5) + (threadIdx.x >> 5); // 0..511
    int lane = threadIdx.x & 31;
    int kb = wg >> 1;
    int mi = wg & 1;

    int q = lane & 3;        // k-quad
    int g = lane >> 2;       // group row
    int r0 = mi * 16 + g;    // token row
    int r1 = r0 + 8;
    int k0 = kb * 16 + 4 * q;

    float4 s  = *(const float4*)(scales + k0);
    float4 x0 = *(const float4*)(x + r0 * IN_F + k0);
    float4 x1 = *(const float4*)(x + r1 * IN_F + k0);

    __half2 h0 = __floats2half2_rn(x0.x * s.x, x0.y * s.y);
    __half2 h1 = __floats2half2_rn(x1.x * s.x, x1.y * s.y);
    __half2 h2 = __floats2half2_rn(x0.z * s.z, x0.w * s.w);
    __half2 h3 = __floats2half2_rn(x1.z * s.z, x1.w * s.w);

    uint4 v;
    v.x = *(const uint32_t*)&h0;
    v.y = *(const uint32_t*)&h1;
    v.z = *(const uint32_t*)&h2;
    v.w = *(const uint32_t*)&h3;
    g_xsfrag[(kb * 2 + mi) * 32 + lane] = v;
}

// ---------------------------------------------------------------------------
// GEMM: 448 CTAs x 128 threads (single wave). CTA owns 32 output features;
// 4 warps split K (1024 each = 64 k16-steps).
// ---------------------------------------------------------------------------
__device__ __forceinline__ void mma16816(float c[4],
    uint32_t a0, uint32_t a1, uint32_t a2, uint32_t a3,
    uint32_t b0, uint32_t b1)
{
    asm volatile(
        "mma.sync.aligned.m16n8k16.row.col.f32.f16.f16.f32 "
        "{%0,%1,%2,%3}, {%4,%5,%6,%7}, {%8,%9}, {%0,%1,%2,%3};\n"
        : "+f"(c[0]), "+f"(c[1]), "+f"(c[2]), "+f"(c[3])
        : "r"(a0), "r"(a1), "r"(a2), "r"(a3), "r"(b0), "r"(b1));
}

__device__ __forceinline__ uint32_t pack_w_h2(int w0, int w1)
{
    __half2 h = __halves2half2(__int2half_rn(w0), __int2half_rn(w1));
    return *(const uint32_t*)&h;
}

#define NWARPS 4
#define KSTEPS (NUM_KB / NWARPS)   // 64 k16-steps per warp

__global__ void __launch_bounds__(128, 4) gemm_q8_kernel(
    const int* __restrict__ W, float* __restrict__ out)
{
    const int lane = threadIdx.x & 31;
    const int warp = threadIdx.x >> 5;    // 0..3, splits K
    const int n0   = blockIdx.x * 32;     // output-feature tile base

    const int q = lane & 3;
    const int g = lane >> 2;

    // accumulators: [mi(2)][nfrag(4)][4]
    float c[2][4][4];
    #pragma unroll
    for (int a = 0; a < 2; a++)
        #pragma unroll
        for (int b = 0; b < 4; b++)
            #pragma unroll
            for (int d = 0; d < 4; d++) c[a][b][d] = 0.0f;

    const int kb0 = warp * KSTEPS;

    // weight base: row = n0 + g (+ j*8), col = 4q (+ kb*16) -- one int4/lane
    const int* wrow = W + (size_t)(n0 + g) * IN_F + 4 * q;

    // ---- software pipeline: current buffers ----
    uint4 A0c, A1c;
    int4  wc[4];
    {
        const int kofs = kb0 * 16;
        A0c = g_xsfrag[(kb0 * 2 + 0) * 32 + lane];
        A1c = g_xsfrag[(kb0 * 2 + 1) * 32 + lane];
        #pragma unroll
        for (int j = 0; j < 4; j++)
            wc[j] = *(const int4*)(wrow + (size_t)j * 8 * IN_F + kofs);
    }

    #pragma unroll 2
    for (int ks = 0; ks < KSTEPS; ks++) {
        // prefetch next iteration (clamped on last iter -> L1-hit reload)
        const int ksn  = (ks + 1 < KSTEPS) ? (ks + 1) : ks;
        const int kbn  = kb0 + ksn;
        const int kofn = kbn * 16;

        uint4 A0n = g_xsfrag[(kbn * 2 + 0) * 32 + lane];
        uint4 A1n = g_xsfrag[(kbn * 2 + 1) * 32 + lane];
        int4  wn[4];
        #pragma unroll
        for (int j = 0; j < 4; j++)
            wn[j] = *(const int4*)(wrow + (size_t)j * 8 * IN_F + kofn);

        // compute on current buffers
        #pragma unroll
        for (int j = 0; j < 4; j++) {
            uint32_t b0 = pack_w_h2(wc[j].x, wc[j].y);
            uint32_t b1 = pack_w_h2(wc[j].z, wc[j].w);
            mma16816(c[0][j], A0c.x, A0c.y, A0c.z, A0c.w, b0, b1);
            mma16816(c[1][j], A1c.x, A1c.y, A1c.z, A1c.w, b0, b1);
        }

        // rotate buffers
        A0c = A0n; A1c = A1n;
        #pragma unroll
        for (int j = 0; j < 4; j++) wc[j] = wn[j];
    }

    // cross-warp K reduction through smem (4 partials)
    __shared__ float red[NWARPS][TOKENS][32];
    #pragma unroll
    for (int mi = 0; mi < 2; mi++) {
        #pragma unroll
        for (int j = 0; j < 4; j++) {
            int row = mi * 16 + g;
            int col = j * 8 + 2 * q;
            *(float2*)&red[warp][row][col]     = make_float2(c[mi][j][0], c[mi][j][1]);
            *(float2*)&red[warp][row + 8][col] = make_float2(c[mi][j][2], c[mi][j][3]);
        }
    }
    __syncthreads();

    // 128 threads: each handles 8 (row,col) outputs
    const int col   = threadIdx.x & 31;
    const int rbase = (threadIdx.x >> 5) * 8;
    #pragma unroll
    for (int i = 0; i < 8; i++) {
        int row = rbase + i;
        float v = red[0][row][col] + red[1][row][col]
                + red[2][row][col] + red[3][row][col];
        out[(size_t)row * OUT_F + n0 + col] = v;
    }
}

// ---------------------------------------------------------------------------
extern "C" void kernel_launch(void* const* d_in, const int* in_sizes, int n_in,
                              void* d_out, int out_size)
{
    const float* x      = (const float*)d_in[0];
    const int*   weight = (const int*)d_in[1];
    const float* scales = (const float*)d_in[2];
    float*       out    = (float*)d_out;

    prep_xs_kernel<<<64, 256>>>(x, scales);
    gemm_q8_kernel<<<448, 128>>>(weight, out);
}

// round 8
// speedup vs baseline: 1.0596x; 1.0596x over previous
#include <cuda_runtime.h>
#include <cuda_fp16.h>
#include <cstdint>

// out[32,14336] = (x * scales) @ W^T
//   x: [32,4096] f32, W: [14336,4096] int32 (|w|<=127), scales: [4096] f32
// HBM-bound: 235MB weight stream -> floor ~29.4us.
// R7: back to 448x256/occ3 (24 warps/SM, best bulk config), W staged through a
// 4-deep per-lane cp.async smem ring -> ~6KB/warp always in flight (vs ~1-2KB
// register pipeline), saturating DRAM and making the 4-CTA tail issue-bound.

#define TOKENS 32
#define IN_F   4096
#define OUT_F  14336
#define NUM_KB (IN_F / 16)      // 256 k16-blocks

// A-fragments of xs=x*scales in fp16, fragment-major (permuted k-layout):
// index ((kb*2 + mi)*32 + lane) -> uint4 (8 fp16 = one m16k16 A frag slice)
__device__ uint4 g_xsfrag[NUM_KB * 2 * 32];

// ---------------------------------------------------------------------------
// Prep: build fragment-major fp16 xs with the permuted k-layout.
// lane quad q owns physical k = kb*16 + 4q .. 4q+3 (one contiguous float4).
// ---------------------------------------------------------------------------
__global__ __launch_bounds__(256) void prep_xs_kernel(
    const float* __restrict__ x, const float* __restrict__ scales)
{
    int wg   = blockIdx.x * (blockDim.x >> 5) + (threadIdx.x >> 5); // 0..511
    int lane = threadIdx.x & 31;
    int kb = wg >> 1;
    int mi = wg & 1;

    int q = lane & 3;        // k-quad
    int g = lane >> 2;       // group row
    int r0 = mi * 16 + g;    // token row
    int r1 = r0 + 8;
    int k0 = kb * 16 + 4 * q;

    float4 s  = *(const float4*)(scales + k0);
    float4 x0 = *(const float4*)(x + r0 * IN_F + k0);
    float4 x1 = *(const float4*)(x + r1 * IN_F + k0);

    __half2 h0 = __floats2half2_rn(x0.x * s.x, x0.y * s.y);
    __half2 h1 = __floats2half2_rn(x1.x * s.x, x1.y * s.y);
    __half2 h2 = __floats2half2_rn(x0.z * s.z, x0.w * s.w);
    __half2 h3 = __floats2half2_rn(x1.z * s.z, x1.w * s.w);

    uint4 v;
    v.x = *(const uint32_t*)&h0;
    v.y = *(const uint32_t*)&h1;
    v.z = *(const uint32_t*)&h2;
    v.w = *(const uint32_t*)&h3;
    g_xsfrag[(kb * 2 + mi) * 32 + lane] = v;
}

// ---------------------------------------------------------------------------
// GEMM helpers
// ---------------------------------------------------------------------------
__device__ __forceinline__ void mma16816(float c[4],
    uint32_t a0, uint32_t a1, uint32_t a2, uint32_t a3,
    uint32_t b0, uint32_t b1)
{
    asm volatile(
        "mma.sync.aligned.m16n8k16.row.col.f32.f16.f16.f32 "
        "{%0,%1,%2,%3}, {%4,%5,%6,%7}, {%8,%9}, {%0,%1,%2,%3};\n"
        : "+f"(c[0]), "+f"(c[1]), "+f"(c[2]), "+f"(c[3])
        : "r"(a0), "r"(a1), "r"(a2), "r"(a3), "r"(b0), "r"(b1));
}

__device__ __forceinline__ uint32_t pack_w_h2(int w0, int w1)
{
    __half2 h = __halves2half2(__int2half_rn(w0), __int2half_rn(w1));
    return *(const uint32_t*)&h;
}

__device__ __forceinline__ void cp_async16(uint32_t dst_smem, const void* src)
{
    asm volatile("cp.async.cg.shared.global [%0], [%1], 16;\n"
                 :: "r"(dst_smem), "l"(src));
}
#define CP_COMMIT() asm volatile("cp.async.commit_group;\n" ::: "memory")
#define CP_WAIT3()  asm volatile("cp.async.wait_group 3;\n" ::: "memory")

#define NWARPS 8
#define KSTEPS (NUM_KB / NWARPS)   // 32 k16-steps per warp
#define STAGES 4
// per warp per stage: 32 lanes * 4 j * 16B = 2048 B
#define STAGE_BYTES   2048
#define WARP_STAGE_SZ (STAGES * STAGE_BYTES)        // 8 KB
#define SMEM_TOTAL    (NWARPS * WARP_STAGE_SZ)      // 64 KB (reused for red)

// ---------------------------------------------------------------------------
// GEMM: 448 CTAs x 256 threads. CTA owns 32 output features; 8 warps split K.
// ---------------------------------------------------------------------------
__global__ void __launch_bounds__(256, 3) gemm_q8_kernel(
    const int* __restrict__ W, float* __restrict__ out)
{
    extern __shared__ char smem_raw[];

    const int lane = threadIdx.x & 31;
    const int warp = threadIdx.x >> 5;    // 0..7, splits K
    const int n0   = blockIdx.x * 32;     // output-feature tile base

    const int q = lane & 3;
    const int g = lane >> 2;

    float c[2][4][4];
    #pragma unroll
    for (int a = 0; a < 2; a++)
        #pragma unroll
        for (int b = 0; b < 4; b++)
            #pragma unroll
            for (int d = 0; d < 4; d++) c[a][b][d] = 0.0f;

    const int kb0 = warp * KSTEPS;

    // weight base: row = n0 + g (+ j*8), col = 4q (+ kb*16) -- one int4/lane
    const int* wrow = W + (size_t)(n0 + g) * IN_F + 4 * q;

    // per-lane staging base (each lane stages only the data it consumes)
    uint32_t smem_u32 = (uint32_t)__cvta_generic_to_shared(smem_raw);
    const uint32_t lanebase = smem_u32 + warp * WARP_STAGE_SZ + lane * 16;

    // ---- prologue: fill STAGES-1 stages ----
    #pragma unroll
    for (int s = 0; s < STAGES - 1; s++) {
        const int kofs = (kb0 + s) * 16;
        const uint32_t slot = lanebase + s * STAGE_BYTES;
        #pragma unroll
        for (int j = 0; j < 4; j++)
            cp_async16(slot + j * 512, wrow + (size_t)j * 8 * IN_F + kofs);
        CP_COMMIT();
    }

    // A fragments current (L2-resident)
    uint4 A0c = g_xsfrag[(kb0 * 2 + 0) * 32 + lane];
    uint4 A1c = g_xsfrag[(kb0 * 2 + 1) * 32 + lane];

    #pragma unroll 4
    for (int ks = 0; ks < KSTEPS; ks++) {
        // issue stage ks+3 (skip past end; commit empty group to keep count)
        const int kpre = ks + STAGES - 1;
        if (kpre < KSTEPS) {
            const int kofs = (kb0 + kpre) * 16;
            const uint32_t slot = lanebase + (kpre & (STAGES - 1)) * STAGE_BYTES;
            #pragma unroll
            for (int j = 0; j < 4; j++)
                cp_async16(slot + j * 512, wrow + (size_t)j * 8 * IN_F + kofs);
        }
        CP_COMMIT();

        // prefetch next A fragments (register one-ahead)
        const int ksn = (ks + 1 < KSTEPS) ? (ks + 1) : ks;
        const int kbn = kb0 + ksn;
        uint4 A0n = g_xsfrag[(kbn * 2 + 0) * 32 + lane];
        uint4 A1n = g_xsfrag[(kbn * 2 + 1) * 32 + lane];

        // wait for stage ks (3 newer groups may still be pending)
        CP_WAIT3();

        const uint32_t slot = lanebase + (ks & (STAGES - 1)) * STAGE_BYTES;
        #pragma unroll
        for (int j = 0; j < 4; j++) {
            int4 wv;
            asm volatile("ld.shared.v4.b32 {%0,%1,%2,%3}, [%4];\n"
                         : "=r"(wv.x), "=r"(wv.y), "=r"(wv.z), "=r"(wv.w)
                         : "r"(slot + j * 512));
            uint32_t b0 = pack_w_h2(wv.x, wv.y);
            uint32_t b1 = pack_w_h2(wv.z, wv.w);
            mma16816(c[0][j], A0c.x, A0c.y, A0c.z, A0c.w, b0, b1);
            mma16816(c[1][j], A1c.x, A1c.y, A1c.z, A1c.w, b0, b1);
        }

        A0c = A0n; A1c = A1n;
    }

    // cross-warp K reduction -- reuse staging smem (all warps done with it)
    __syncthreads();
    float (*red)[TOKENS][32] = (float (*)[TOKENS][32])smem_raw;
    #pragma unroll
    for (int mi = 0; mi < 2; mi++) {
        #pragma unroll
        for (int j = 0; j < 4; j++) {
            int row = mi * 16 + g;
            int col = j * 8 + 2 * q;
            *(float2*)&red[warp][row][col]     = make_float2(c[mi][j][0], c[mi][j][1]);
            *(float2*)&red[warp][row + 8][col] = make_float2(c[mi][j][2], c[mi][j][3]);
        }
    }
    __syncthreads();

    // 256 threads: each handles 4 (row,col) outputs
    const int col   = threadIdx.x & 31;
    const int rbase = (threadIdx.x >> 5) * 4;
    #pragma unroll
    for (int i = 0; i < 4; i++) {
        int row = rbase + i;
        float v = 0.0f;
        #pragma unroll
        for (int w = 0; w < NWARPS; w++) v += red[w][row][col];
        out[(size_t)row * OUT_F + n0 + col] = v;
    }
}

// ---------------------------------------------------------------------------
extern "C" void kernel_launch(void* const* d_in, const int* in_sizes, int n_in,
                              void* d_out, int out_size)
{
    const float* x      = (const float*)d_in[0];
    const int*   weight = (const int*)d_in[1];
    const float* scales = (const float*)d_in[2];
    float*       out    = (float*)d_out;

    cudaFuncSetAttribute(gemm_q8_kernel,
                         cudaFuncAttributeMaxDynamicSharedMemorySize, SMEM_TOTAL);

    prep_xs_kernel<<<64, 256>>>(x, scales);
    gemm_q8_kernel<<<448, 256, SMEM_TOTAL>>>(weight, out);
}